// round 1
// baseline (speedup 1.0000x reference)
#include <cuda_runtime.h>
#include <cuda_bf16.h>
#include <math.h>

// Problem dims
#define Bc 4096
#define Tc 128
#define Vc 30
#define Ec 256
#define Hc 128
#define Gc 512      // 4*H gates
#define NBLK 32     // batch rows per block
#define NTHR 512

// Scratch (no cudaMalloc allowed)
__device__ float  d_EW[Vc * Gc];   // precomputed x-side gates per vocab id
__device__ double d_loss_sum;
__device__ double d_mask_sum;

__global__ void zero_kernel() {
    d_loss_sum = 0.0;
    d_mask_sum = 0.0;
}

// EW[v][j] = b_ih[j] + b_hh[j] + sum_e W_ih[j][e] * emb[v][e]
__global__ void ew_kernel(const float* __restrict__ emb,
                          const float* __restrict__ W_ih,
                          const float* __restrict__ b_ih,
                          const float* __restrict__ b_hh) {
    __shared__ float ev[Ec];
    int v = blockIdx.x;
    int j = threadIdx.x;
    for (int e = threadIdx.x; e < Ec; e += blockDim.x) ev[e] = emb[v * Ec + e];
    __syncthreads();
    float s = b_ih[j] + b_hh[j];
    const float* w = W_ih + j * Ec;
#pragma unroll 8
    for (int e = 0; e < Ec; e++) s += w[e] * ev[e];
    d_EW[v * Gc + j] = s;
}

__global__ void mask_sum_kernel(const float* __restrict__ mask, int n) {
    double local = 0.0;
    for (int i = blockIdx.x * blockDim.x + threadIdx.x; i < n;
         i += gridDim.x * blockDim.x)
        local += (double)mask[i];
#pragma unroll
    for (int o = 16; o; o >>= 1) local += __shfl_down_sync(0xffffffffu, local, o);
    __shared__ double ws[32];
    int lane = threadIdx.x & 31, w = threadIdx.x >> 5;
    if (lane == 0) ws[w] = local;
    __syncthreads();
    if (w == 0) {
        local = (lane < (int)(blockDim.x >> 5)) ? ws[lane] : 0.0;
#pragma unroll
        for (int o = 16; o; o >>= 1) local += __shfl_down_sync(0xffffffffu, local, o);
        if (lane == 0) atomicAdd(&d_mask_sum, local);
    }
}

// Main recurrent kernel. One CTA owns NBLK=32 batch rows for all 127 steps.
// SMEM: W_hh as bf16x2 (k-major), h[32][128] fp32, W_lin (k-major, padded to 32 v).
// Thread tid: hidden unit u = tid&127, batch group bgrp = tid>>7 (8 rows each).
// Each thread computes all 4 gates for (u, 8 batch rows); c lives in registers.
__global__ void __launch_bounds__(NTHR, 1)
lstm_kernel(const int* __restrict__ inpt,
            const float* __restrict__ h0,
            const float* __restrict__ c0,
            const float* __restrict__ mask,
            const float* __restrict__ W_hh,
            const float* __restrict__ W_lin,
            const float* __restrict__ b_lin) {
    extern __shared__ char smem[];
    __nv_bfloat162* whh2 = (__nv_bfloat162*)smem;                 // [64][512]
    float* h_s = (float*)(smem + 64 * Gc * sizeof(__nv_bfloat162)); // [32][128]
    float* wl  = h_s + NBLK * Hc;                                  // [128][32]
    float* bl  = wl + Hc * 32;                                     // [32]

    const int tid  = threadIdx.x;
    const int lane = tid & 31;
    const int warp = tid >> 5;
    const int u    = tid & 127;
    const int bgrp = tid >> 7;          // 0..3 (constant within a warp)
    const int b0   = blockIdx.x * NBLK;

    // Load W_hh -> bf16x2, k-major: whh2[kk][j] = (W[j][2kk], W[j][2kk+1])
    for (int idx = tid; idx < Gc * 64; idx += NTHR) {
        int j  = idx & (Gc - 1);
        int kk = idx >> 9;
        float2 wv = *(const float2*)&W_hh[j * Hc + 2 * kk];
        whh2[kk * Gc + j] = __floats2bfloat162_rn(wv.x, wv.y);
    }
    // W_lin k-major, v padded to 32 (pad entries zeroed)
    for (int idx = tid; idx < Hc * 32; idx += NTHR) wl[idx] = 0.f;
    __syncthreads();
    for (int idx = tid; idx < Vc * Hc; idx += NTHR) {
        int v = idx / Hc, k = idx % Hc;
        wl[k * 32 + v] = W_lin[idx];
    }
    if (tid < 32) bl[tid] = (tid < Vc) ? b_lin[tid] : 0.f;

    for (int idx = tid; idx < NBLK * Hc; idx += NTHR)
        h_s[idx] = h0[b0 * Hc + idx];

    float c_reg[8];
#pragma unroll
    for (int i = 0; i < 8; i++)
        c_reg[i] = c0[(b0 + bgrp * 8 + i) * Hc + u];

    float my_loss = 0.f;
    __syncthreads();

    for (int t = 0; t < Tc - 1; t++) {
        // ---- gates = EW[token] + h @ W_hh^T ----
        float acc[4][8];
#pragma unroll
        for (int i = 0; i < 8; i++) {
            int tk = inpt[(b0 + bgrp * 8 + i) * Tc + t];
            const float* er = d_EW + tk * Gc;
            acc[0][i] = er[u];
            acc[1][i] = er[u + 128];
            acc[2][i] = er[u + 256];
            acc[3][i] = er[u + 384];
        }
#pragma unroll 2
        for (int kk = 0; kk < 64; kk++) {
            float2 w0 = __bfloat1622float2(whh2[kk * Gc + u]);
            float2 w1 = __bfloat1622float2(whh2[kk * Gc + u + 128]);
            float2 w2 = __bfloat1622float2(whh2[kk * Gc + u + 256]);
            float2 w3 = __bfloat1622float2(whh2[kk * Gc + u + 384]);
#pragma unroll
            for (int i = 0; i < 8; i++) {
                float2 hb = *(const float2*)&h_s[(bgrp * 8 + i) * Hc + 2 * kk];
                acc[0][i] += w0.x * hb.x; acc[0][i] += w0.y * hb.y;
                acc[1][i] += w1.x * hb.x; acc[1][i] += w1.y * hb.y;
                acc[2][i] += w2.x * hb.x; acc[2][i] += w2.y * hb.y;
                acc[3][i] += w3.x * hb.x; acc[3][i] += w3.y * hb.y;
            }
        }
        // ---- LSTM cell (c in registers) ----
        float h2v[8];
#pragma unroll
        for (int i = 0; i < 8; i++) {
            float ig = 1.f / (1.f + expf(-acc[0][i]));
            float fg = 1.f / (1.f + expf(-acc[1][i]));
            float gg = tanhf(acc[2][i]);
            float og = 1.f / (1.f + expf(-acc[3][i]));
            float c2 = fg * c_reg[i] + ig * gg;
            c_reg[i] = c2;
            h2v[i] = og * tanhf(c2);
        }
        __syncthreads();   // everyone done reading old h_s
#pragma unroll
        for (int i = 0; i < 8; i++)
            h_s[(bgrp * 8 + i) * Hc + u] = h2v[i];
        __syncthreads();   // new h visible

        // ---- logits + log-softmax CE: one warp handles 2 batch rows ----
#pragma unroll
        for (int bi = 0; bi < 2; bi++) {
            int brow = warp * 2 + bi;
            float logit = (lane < Vc) ? bl[lane] : -INFINITY;
            const float* hrow = &h_s[brow * Hc];
#pragma unroll 4
            for (int k4 = 0; k4 < 32; k4++) {
                float4 hv = *(const float4*)&hrow[4 * k4];
                float wv0 = wl[(4 * k4 + 0) * 32 + lane];
                float wv1 = wl[(4 * k4 + 1) * 32 + lane];
                float wv2 = wl[(4 * k4 + 2) * 32 + lane];
                float wv3 = wl[(4 * k4 + 3) * 32 + lane];
                logit += hv.x * wv0 + hv.y * wv1 + hv.z * wv2 + hv.w * wv3;
            }
            float mx = logit;
#pragma unroll
            for (int o = 16; o; o >>= 1)
                mx = fmaxf(mx, __shfl_xor_sync(0xffffffffu, mx, o));
            float ex = (lane < Vc) ? expf(logit - mx) : 0.f;
            float sum = ex;
#pragma unroll
            for (int o = 16; o; o >>= 1)
                sum += __shfl_xor_sync(0xffffffffu, sum, o);
            int y = inpt[(b0 + brow) * Tc + t + 1];
            float ly = __shfl_sync(0xffffffffu, logit, y);
            if (lane == 0) {
                float m = mask[(b0 + brow) * Tc + t];
                my_loss += (mx + logf(sum) - ly) * m;
            }
        }
    }

    // block-reduce loss, one atomic per block
#pragma unroll
    for (int o = 16; o; o >>= 1)
        my_loss += __shfl_xor_sync(0xffffffffu, my_loss, o);
    __shared__ float wsum[16];
    if (lane == 0) wsum[warp] = my_loss;
    __syncthreads();
    if (warp == 0) {
        float v = (lane < 16) ? wsum[lane] : 0.f;
#pragma unroll
        for (int o = 8; o; o >>= 1)
            v += __shfl_xor_sync(0xffffffffu, v, o);
        if (lane == 0) atomicAdd(&d_loss_sum, (double)v);
    }
}

__global__ void finalize_kernel(float* out) {
    out[0] = (float)(d_loss_sum / d_mask_sum);
}

extern "C" void kernel_launch(void* const* d_in, const int* in_sizes, int n_in,
                              void* d_out, int out_size) {
    const int*   inpt  = (const int*)d_in[0];
    const float* h0    = (const float*)d_in[1];
    const float* c0    = (const float*)d_in[2];
    const float* mask  = (const float*)d_in[3];
    // d_in[4] = beta (unused by reference)
    const float* emb   = (const float*)d_in[5];
    const float* W_ih  = (const float*)d_in[6];
    const float* b_ih  = (const float*)d_in[7];
    const float* W_hh  = (const float*)d_in[8];
    const float* b_hh  = (const float*)d_in[9];
    const float* W_lin = (const float*)d_in[10];
    const float* b_lin = (const float*)d_in[11];
    float* out = (float*)d_out;

    const size_t smem_main = 64 * Gc * sizeof(__nv_bfloat162)  // 131072
                           + NBLK * Hc * sizeof(float)          // 16384
                           + Hc * 32 * sizeof(float)            // 16384
                           + 32 * sizeof(float);                // 128
    cudaFuncSetAttribute(lstm_kernel,
                         cudaFuncAttributeMaxDynamicSharedMemorySize,
                         (int)smem_main);

    zero_kernel<<<1, 1>>>();
    mask_sum_kernel<<<256, 256>>>(mask, Bc * Tc);
    ew_kernel<<<Vc, Gc>>>(emb, W_ih, b_ih, b_hh);
    lstm_kernel<<<Bc / NBLK, NTHR, smem_main>>>(inpt, h0, c0, mask,
                                                W_hh, W_lin, b_lin);
    finalize_kernel<<<1, 1>>>(out);
}